// round 14
// baseline (speedup 1.0000x reference)
#include <cuda_runtime.h>
#include <cuda_bf16.h>
#include <math.h>

// ---------------- constants ----------------
#define KNN     5
#define KK      6        // K+1, self included then dropped
#define MAXPTS  65536
#define MAXB    64
#define SORTN   2048
#define WIN     64       // window half-width (64 validated; 48 = flag-rate cliff)
#define TILE    (128 + 4 * WIN + 2)

// ---------------- device scratch ----------------
// (fallback path only)
__device__ float g_x[MAXPTS];
__device__ float g_z[MAXPTS];
__device__ float g_h[MAXPTS];
__device__ float g_sq[MAXPTS];
__device__ unsigned char g_valid[MAXPTS];

// sorted-by-z per batch, packed: (x, z, h, sq)
__device__ float4 gs_p[MAXB * SORTN];

__device__ int   g_nflag[MAXB];
__device__ int   g_flag[MAXB * SORTN];
__device__ float g_flagthr[MAXB * SORTN];   // certified 6th-NN d2 upper bound

__device__ int   g_validn[MAXB];
__device__ float g_Sh[MAXB];
__device__ float g_Sls[MAXB];
__device__ float g_Ssl[MAXB];

// [0]=sum(sc) [1]=sum(ydiff*sc) [2]=sum(ydiff) [3]=sum(w) [4]=sum(diff*w) [5]=sum(sl1*w)
__device__ float g_acc[8];
__device__ int   g_cnt;
__device__ int   g_done;

// ---------------- helpers ----------------
__device__ __forceinline__ float smooth_l1f(float x, float y, float beta) {
    float d = fabsf(x - y);
    return d < beta ? 0.5f * d * d / beta : d - 0.5f * beta;
}

__device__ __forceinline__ float bilinear_ref(const float* __restrict__ im,
                                              float x, float y, int W, int H) {
    x = fminf(fmaxf(x, 0.f), (float)(W - 1));
    y = fminf(fmaxf(y, 0.f), (float)(H - 1));
    float x0 = floorf(x), y0 = floorf(y);
    float fx = x - x0, fy = y - y0;
    int x0i = min(max((int)x0, 0), W - 1);
    int x1i = min(x0i + 1, W - 1);
    int y0i = min(max((int)y0, 0), H - 1);
    int y1i = min(y0i + 1, H - 1);
    float v00 = __ldg(im + (size_t)y0i * W + x0i);
    float v01 = __ldg(im + (size_t)y0i * W + x1i);
    float v10 = __ldg(im + (size_t)y1i * W + x0i);
    float v11 = __ldg(im + (size_t)y1i * W + x1i);
    float top = v00 * (1.f - fx) + v01 * fx;
    float bot = v10 * (1.f - fx) + v11 * fx;
    return top * (1.f - fy) + bot * fy;
}

__device__ __forceinline__ void sample_pair(const float* __restrict__ im,
                                            float cx, float cy, int W, int H,
                                            int lane, float& t0, float& t1) {
    float fix = floorf(cx), fiy = floorf(cy);
    float fx = cx - fix, fy = cy - fiy;
    int ix = (int)fix, iy = (int)fiy;
    int r = lane >> 2, cg = (lane & 3) << 1;
    bool fast = (ix >= 3) && (ix + 4 <= W - 1) && (iy >= 3) && (iy + 4 <= H - 1);
    if (fast) {
        const float* rp = im + (size_t)(iy - 3 + r) * W + (ix - 3 + cg);
        float w0 = __ldg(rp);
        float w1 = __ldg(rp + 1);
        float w2 = __shfl_down_sync(0xffffffffu, w0, 1);
        float ci0 = fmaf(fx, w1 - w0, w0);
        float ci1 = fmaf(fx, w2 - w1, w1);
        float cj0 = __shfl_down_sync(0xffffffffu, ci0, 4);
        float cj1 = __shfl_down_sync(0xffffffffu, ci1, 4);
        t0 = fmaf(fy, cj0 - ci0, ci0);
        t1 = fmaf(fy, cj1 - ci1, ci1);
    } else {
        t0 = bilinear_ref(im, cx + (float)(cg - 3), cy + (float)(r - 3), W, H);
        t1 = bilinear_ref(im, cx + (float)(cg - 2), cy + (float)(r - 3), W, H);
    }
}

// geometry for point p of batch b; returns valid
__device__ __forceinline__ bool geom(const float* __restrict__ kpl,
                                     const float* __restrict__ kpr,
                                     const float* __restrict__ scores,
                                     const float* __restrict__ Qb,
                                     int p, float& pmx, float& pmz,
                                     float& hh, float& sq) {
    float klx = __ldg(kpl + 2 * p), kly = __ldg(kpl + 2 * p + 1);
    float krx = __ldg(kpr + 2 * p);
    float sc  = __ldg(scores + p);
    float disp = klx - krx;
    float p0 = __ldg(Qb+0)  * klx + __ldg(Qb+1)  * kly + __ldg(Qb+2)  * disp + __ldg(Qb+3);
    float p1 = __ldg(Qb+4)  * klx + __ldg(Qb+5)  * kly + __ldg(Qb+6)  * disp + __ldg(Qb+7);
    float p2 = __ldg(Qb+8)  * klx + __ldg(Qb+9)  * kly + __ldg(Qb+10) * disp + __ldg(Qb+11);
    float p3 = __ldg(Qb+12) * klx + __ldg(Qb+13) * kly + __ldg(Qb+14) * disp + __ldg(Qb+15);
    float Wc = fmaxf(p3, 1e-6f);
    float X = p0 / Wc, Y = p1 / Wc, Z = p2 / Wc;
    bool valid = (Z > 100.f) && (Z < 30000.f) && (sc > 0.1f);
    pmx = X / 1000.f;
    hh  = Y / 1000.f;
    pmz = Z / 1000.f;
    sq  = pmx * pmx + pmz * pmz;
    return valid;
}

// sorted-insert (ascending) into static-indexed 6-lists
#define INSERT6(d2, hv)                                                     \
    if ((d2) < d2k[KK - 1]) {                                               \
        d2k[KK - 1] = (d2); hk[KK - 1] = (hv);                              \
        _Pragma("unroll")                                                   \
        for (int _k = KK - 1; _k > 0; _k--) {                               \
            if (d2k[_k] < d2k[_k - 1]) {                                    \
                float _td = d2k[_k]; d2k[_k] = d2k[_k-1]; d2k[_k-1] = _td;  \
                float _th = hk[_k];  hk[_k]  = hk[_k-1];  hk[_k-1]  = _th;  \
            }                                                               \
        }                                                                   \
    }

// ---------------- kernel 0: zero accumulators (fallback path only) ---------
__global__ void zero_kernel() {
    int t = threadIdx.x;
    if (t < 8)   g_acc[t] = 0.f;
    if (t == 8)  g_cnt = 0;
    if (t == 9)  g_done = 0;
    if (t < MAXB) {
        g_validn[t] = 0;
        g_nflag[t]  = 0;
        g_Sls[t] = 0.f;
        g_Ssl[t] = 0.f;
        g_Sh[t]  = 0.f;
    }
}

// ---------------- kernel G: fused zero + geometry + z-sort (block per batch)
__global__ void geom_sort_kernel(const float* __restrict__ kpl,
                                 const float* __restrict__ kpr,
                                 const float* __restrict__ scores,
                                 const float* __restrict__ Q, int N) {
    __shared__ unsigned long long pack[SORTN];          // (z bits << 32) | idx
    __shared__ float sxv[SORTN], shv[SORTN], sqv[SORTN];
    __shared__ float warpH[32];
    __shared__ int   warpC[32];
    int b   = blockIdx.x;
    int tid = threadIdx.x;   // 1024
    const float* Qb = Q + (size_t)b * 16;

    if (tid == 0) {
        g_nflag[b] = 0;
        g_Sls[b] = 0.f;
        g_Ssl[b] = 0.f;
    }
    if (b == 0) {
        if (tid < 8)  g_acc[tid] = 0.f;
        if (tid == 8) g_cnt = 0;
        if (tid == 9) g_done = 0;
    }

    int   cLoc = 0;
    float hLoc = 0.f;
    #pragma unroll
    for (int it = 0; it < SORTN / 1024; it++) {
        int i = tid + it * 1024;
        float key;
        if (i < N) {
            float pmx, pmz, hh, sq;
            bool valid = geom(kpl, kpr, scores, Qb, b * N + i, pmx, pmz, hh, sq);
            sxv[i] = pmx; shv[i] = hh; sqv[i] = sq;
            key = valid ? pmz : 1e30f;
            if (valid) { cLoc++; hLoc += hh; }
        } else {
            sxv[i] = 0.f; shv[i] = 0.f; sqv[i] = 4e18f;
            key = 3e30f;
        }
        pack[i] = ((unsigned long long)__float_as_uint(key) << 32) | (unsigned)i;
    }
    #pragma unroll
    for (int o = 16; o > 0; o >>= 1) {
        cLoc += __shfl_down_sync(0xffffffffu, cLoc, o);
        hLoc += __shfl_down_sync(0xffffffffu, hLoc, o);
    }
    if ((tid & 31) == 0) { warpC[tid >> 5] = cLoc; warpH[tid >> 5] = hLoc; }
    __syncthreads();
    if (tid == 0) {
        int cT = 0; float hT = 0.f;
        #pragma unroll
        for (int wv = 0; wv < 32; wv++) { cT += warpC[wv]; hT += warpH[wv]; }
        g_validn[b] = cT;
        g_Sh[b]     = hT;
    }

    for (int k = 2; k <= SORTN; k <<= 1) {
        for (int j = k >> 1; j > 0; j >>= 1) {
            #pragma unroll
            for (int it = 0; it < SORTN / 1024; it++) {
                int i = tid + it * 1024;
                int ixj = i ^ j;
                if (ixj > i) {
                    unsigned long long a = pack[i], c = pack[ixj];
                    bool up = ((i & k) == 0);
                    if ((a > c) == up) { pack[i] = c; pack[ixj] = a; }
                }
            }
            __syncthreads();
        }
    }

    #pragma unroll
    for (int it = 0; it < SORTN / 1024; it++) {
        int i = tid + it * 1024;
        unsigned long long v = pack[i];
        int idx = (int)(v & 0xffffffffu);
        float zz = __uint_as_float((unsigned)(v >> 32));
        gs_p[b * SORTN + i] = make_float4(sxv[idx], zz, shv[idx], sqv[idx]);
    }
}

// ---------------- kernel 2b: split-window 6-NN over z-sorted VALID prefix ----
__global__ void knn_window_kernel(int B, int N) {
    __shared__ float sx[TILE], sz[TILE], sh[TILE], sq[TILE];
    __shared__ float lists[256][2 * KK];
    __shared__ float sls, ssl;
    int b    = blockIdx.y;
    int tid  = threadIdx.x;      // 256
    int t    = tid & 127;
    int half = tid >> 7;
    int blockStart = blockIdx.x * 128;
    int n    = blockStart + t;
    int base = b * SORTN;

    int nv = g_validn[b];
    int tl = max(0, blockStart - 2 * WIN - 1);
    int th = min(nv, blockStart + 128 + 2 * WIN + 1);
    int cnt = max(0, th - tl);
    for (int i = tid; i < cnt; i += 256) {
        float4 v = gs_p[base + tl + i];
        sx[i] = v.x; sz[i] = v.y; sh[i] = v.z; sq[i] = v.w;
    }
    if (tid == 0) { sls = 0.f; ssl = 0.f; }
    __syncthreads();

    bool active = (n < nv);

    float d2k[KK], hk[KK];
    #pragma unroll
    for (int k = 0; k < KK; k++) { d2k[k] = 3.4e38f; hk[k] = 0.f; }

    int lo = 0, hi = 0;
    float xn = 0.f, zn = 0.f, hn = 0.f, sqn = 0.f;
    if (active) {
        xn = sx[n - tl]; zn = sz[n - tl]; hn = sh[n - tl]; sqn = sq[n - tl];

        lo = n - WIN;
        hi = n + WIN;
        if (lo < 0)  { hi -= lo; lo = 0; }
        if (hi > nv) { lo -= (hi - nv); hi = nv; if (lo < 0) lo = 0; }

        int mid = (lo + hi) >> 1;
        int beg = half ? mid : lo;
        int end = half ? hi  : mid;

        for (int j = beg; j < end; j++) {
            int ji = j - tl;
            float d2 = sqn + sq[ji] - 2.f * (xn * sx[ji] + zn * sz[ji]);
            INSERT6(d2, sh[ji]);
        }
    }
    #pragma unroll
    for (int k = 0; k < KK; k++) {
        lists[tid][k]      = d2k[k];
        lists[tid][KK + k] = hk[k];
    }
    __syncthreads();

    float ls = 0.f, pensum = 0.f;
    if (tid < 128 && active) {
        const float* pa = lists[tid];
        const float* pb = lists[tid + 128];
        float md[KK], mh[KK];
        int ia = 0, ib = 0;
        #pragma unroll
        for (int k = 0; k < KK; k++) {
            float da = pa[ia], db = pb[ib];
            bool ta = (da <= db);
            md[k] = ta ? da : db;
            mh[k] = ta ? pa[KK + ia] : pb[KK + ib];
            ia += ta ? 1 : 0;
            ib += ta ? 0 : 1;
        }

        float thr = md[KK - 1] * 1.0001f + 1e-9f;
        bool bad = false;
        if (lo > 0)  { float dz = zn - sz[lo - 1 - tl]; if (dz * dz <= thr) bad = true; }
        if (hi < nv) { float dz = sz[hi - tl] - zn;     if (dz * dz <= thr) bad = true; }

        if (bad) {
            int slot = atomicAdd(&g_nflag[b], 1);
            g_flag[base + slot]    = n;
            g_flagthr[base + slot] = thr;
        } else {
            float lm = (mh[1] + mh[2] + mh[3] + mh[4] + mh[5]) / 5.f;
            ls = smooth_l1f(hn, lm, 0.01f);
            #pragma unroll
            for (int k = 1; k < KK; k++) {
                float nd = fmaxf(sqrtf(fmaxf(md[k], 1e-12f)), 0.001f);
                float s  = fabsf(mh[k] - hn) / nd;
                pensum  += fmaxf(s - 0.4f, 0.f);
            }
        }
    }

    #pragma unroll
    for (int o = 16; o > 0; o >>= 1) {
        ls     += __shfl_down_sync(0xffffffffu, ls, o);
        pensum += __shfl_down_sync(0xffffffffu, pensum, o);
    }
    if ((tid & 31) == 0) {
        atomicAdd(&sls, ls);
        atomicAdd(&ssl, pensum);
    }
    __syncthreads();
    if (tid == 0) {
        atomicAdd(&g_Sls[b], sls);
        atomicAdd(&g_Ssl[b], ssl);
    }
}

// ---------------- finalize (device function, run by one warp) ----------------
__device__ __forceinline__ void do_finalize(float* __restrict__ out, int B, int N, int t) {
    float s_ls = 0.f, s_sl = 0.f, s_lz = 0.f, s_ok = 0.f;
    for (int b = t; b < B; b += 32) {
        int nvi  = g_validn[b];
        float nv = (float)max(nvi, 1);
        float ok = (nvi >= 10) ? 1.f : 0.f;
        s_ls += ok * (g_Sls[b] / nv);
        s_sl += ok * (g_Ssl[b] / (nv * (float)KNN));
        s_lz += ok * fabsf(g_Sh[b] / nv);
        s_ok += ok;
    }
    float accv = (t < 6) ? g_acc[t] : 0.f;
    int   cntv = g_cnt;
    #pragma unroll
    for (int o = 16; o > 0; o >>= 1) {
        s_ls += __shfl_down_sync(0xffffffffu, s_ls, o);
        s_sl += __shfl_down_sync(0xffffffffu, s_sl, o);
        s_lz += __shfl_down_sync(0xffffffffu, s_lz, o);
        s_ok += __shfl_down_sync(0xffffffffu, s_ok, o);
    }
    float a0 = __shfl_sync(0xffffffffu, accv, 0);
    float a1 = __shfl_sync(0xffffffffu, accv, 1);
    float a2 = __shfl_sync(0xffffffffu, accv, 2);
    float a3 = __shfl_sync(0xffffffffu, accv, 3);
    float a4 = __shfl_sync(0xffffffffu, accv, 4);
    float a5 = __shfl_sync(0xffffffffu, accv, 5);
    if (t == 0) {
        float l_epi = (a0 > 0.0001f) ? (a1 / fmaxf(a0, 1e-12f))
                                     : (a2 / (float)(B * N));
        float safe = fmaxf(a3, 1e-12f);
        float l_masked    = (a3 > 0.0001f) ? (a4 / safe) : 0.f;
        float l_intensity = (a3 > 0.0001f) ? (a5 / safe) : 0.f;

        float nb = fmaxf(s_ok, 1.f);
        bool gate = (cntv >= 10) && (s_ok > 0.f);

        out[0] = l_masked + l_intensity;
        out[1] = l_epi;
        out[2] = gate ? (s_ls / nb) : 0.f;
        out[3] = gate ? (s_sl / nb) : 0.f;
        out[4] = gate ? (s_lz / nb) : 0.f;
    }
}

// ---------------- kernel PF: fused photo + flagged-point scan + finalize -----
// grid = blocks1 (covers photo: warp per point). Flag work strided over ALL
// warps of the grid (<=1 flagged point per warp typical). Ticket finalize.
__global__ void photo_flag_kernel(float* __restrict__ out,
                                  const float* __restrict__ lg,
                                  const float* __restrict__ rg,
                                  const float* __restrict__ kpl,
                                  const float* __restrict__ kpr,
                                  const float* __restrict__ scores,
                                  int B, int N, int H, int W, int totalBlocks) {
    __shared__ float sacc[6];
    __shared__ int   scnt;
    __shared__ int   isLast;
    int tid  = threadIdx.x;
    int warp = tid >> 5;
    int lane = tid & 31;
    if (tid < 6) sacc[tid] = 0.f;
    if (tid == 6) scnt = 0;
    __syncthreads();

    // ---- phase A: photo (warp per point) ----
    int total = B * N;
    int p = blockIdx.x * 8 + warp;
    if (p < total) {
        int b = p / N;
        float klx = __ldg(kpl + 2 * p),  kly = __ldg(kpl + 2 * p + 1);
        float krx = __ldg(kpr + 2 * p),  kry = __ldg(kpr + 2 * p + 1);
        float sc  = __ldg(scores + p);

        const float* L = lg + (size_t)b * H * W;
        const float* R = rg + (size_t)b * H * W;
        float tl0, tl1, tr0, tr1;
        sample_pair(L, klx, kly, W, H, lane, tl0, tl1);
        sample_pair(R, krx, kry, W, H, lane, tr0, tr1);

        int r = lane >> 2;
        float a = 0.f;
        if (r < 7) {
            a = fabsf(tl0 - tr0);
            if ((lane & 3) < 3) a += fabsf(tl1 - tr1);
        }
        #pragma unroll
        for (int o = 16; o > 0; o >>= 1)
            a += __shfl_down_sync(0xffffffffu, a, o);

        float cl = __shfl_sync(0xffffffffu, tl1, 13);
        float cr = __shfl_sync(0xffffffffu, tr1, 13);

        if (lane == 0) {
            float diffm = a / 49.f;
            float isb   = (cl > 0.02f) ? 1.f : 0.f;
            float w     = sc * isb;
            float ydiff = fabsf(kly - kry);
            atomicAdd(&sacc[0], sc);
            atomicAdd(&sacc[1], ydiff * sc);
            atomicAdd(&sacc[2], ydiff);
            atomicAdd(&sacc[3], w);
            atomicAdd(&sacc[4], diffm * w);
            atomicAdd(&sacc[5], smooth_l1f(cl, cr, 1.f) * w);
            if (sc > 0.1f) atomicAdd(&scnt, 1);
        }
    }

    // ---- phase B: flagged-point exact z-bounded scan (grid-strided) ----
    {
        int gWarp = blockIdx.x * 8 + warp;
        int totalWarps = totalBlocks * 8;
        for (int b = 0; b < B; b++) {
            int nf = g_nflag[b];
            if (nf == 0) continue;
            int base = b * SORTN;
            int nv = g_validn[b];
            const float4* P = gs_p + base;
            for (int f = gWarp; f < nf; f += totalWarps) {
                int n = g_flag[base + f];
                float thr0 = g_flagthr[base + f];
                float4 me = __ldg(&P[n]);
                float xn = me.x, zn = me.y, hn = me.z, sqn = me.w;

                float dzmax = sqrtf(thr0);
                float zLo = zn - dzmax, zHi = zn + dzmax;
                int lo = 0, hiB = nv;
                while (lo < hiB) { int m = (lo + hiB) >> 1; if (__ldg(&P[m]).y < zLo) lo = m + 1; else hiB = m; }
                int jlo = lo;
                lo = jlo; hiB = nv;
                while (lo < hiB) { int m = (lo + hiB) >> 1; if (__ldg(&P[m]).y <= zHi) lo = m + 1; else hiB = m; }
                int jhi = lo;

                float d2k[KK], hk[KK];
                #pragma unroll
                for (int k = 0; k < KK; k++) { d2k[k] = 3.4e38f; hk[k] = 0.f; }

                int j = jlo + lane;
                for (; j + 96 < jhi; j += 128) {
                    float4 v0 = __ldg(&P[j]);
                    float4 v1 = __ldg(&P[j + 32]);
                    float4 v2 = __ldg(&P[j + 64]);
                    float4 v3 = __ldg(&P[j + 96]);
                    float d0 = sqn + v0.w - 2.f * (xn * v0.x + zn * v0.y);
                    float d1 = sqn + v1.w - 2.f * (xn * v1.x + zn * v1.y);
                    float d2_ = sqn + v2.w - 2.f * (xn * v2.x + zn * v2.y);
                    float d3 = sqn + v3.w - 2.f * (xn * v3.x + zn * v3.y);
                    INSERT6(d0, v0.z);
                    INSERT6(d1, v1.z);
                    INSERT6(d2_, v2.z);
                    INSERT6(d3, v3.z);
                }
                for (; j < jhi; j += 32) {
                    float4 v = __ldg(&P[j]);
                    float d2 = sqn + v.w - 2.f * (xn * v.x + zn * v.y);
                    INSERT6(d2, v.z);
                }

                float md[KK], mh[KK];
                #pragma unroll
                for (int r2 = 0; r2 < KK; r2++) {
                    float v  = d2k[0];
                    float mv = v;
                    #pragma unroll
                    for (int o = 16; o > 0; o >>= 1)
                        mv = fminf(mv, __shfl_xor_sync(0xffffffffu, mv, o));
                    unsigned msk = __ballot_sync(0xffffffffu, v == mv);
                    int src = __ffs(msk) - 1;
                    float hh0 = hk[0];
                    float mhh = __shfl_sync(0xffffffffu, hh0, src);
                    if (lane == src) {
                        #pragma unroll
                        for (int k = 0; k < KK - 1; k++) { d2k[k] = d2k[k + 1]; hk[k] = hk[k + 1]; }
                        d2k[KK - 1] = 3.4e38f; hk[KK - 1] = 0.f;
                    }
                    md[r2] = mv; mh[r2] = mhh;
                }

                if (lane == 0) {
                    float lm = (mh[1] + mh[2] + mh[3] + mh[4] + mh[5]) / 5.f;
                    float lsv = smooth_l1f(hn, lm, 0.01f);
                    float pen = 0.f;
                    #pragma unroll
                    for (int k = 1; k < KK; k++) {
                        float nd = fmaxf(sqrtf(fmaxf(md[k], 1e-12f)), 0.001f);
                        float s  = fabsf(mh[k] - hn) / nd;
                        pen += fmaxf(s - 0.4f, 0.f);
                    }
                    atomicAdd(&g_Sls[b], lsv);
                    atomicAdd(&g_Ssl[b], pen);
                }
            }
        }
    }

    // ---- phase C: block-level commit + ticket + finalize ----
    __syncthreads();
    if (tid < 6) atomicAdd(&g_acc[tid], sacc[tid]);
    if (tid == 6 && scnt) atomicAdd(&g_cnt, scnt);
    __syncthreads();
    if (tid == 0) {
        __threadfence();
        int v = atomicAdd(&g_done, 1);
        isLast = (v == totalBlocks - 1) ? 1 : 0;
    }
    __syncthreads();
    if (isLast && tid < 32) {
        do_finalize(out, B, N, tid);
    }
}

// ---------------- fallback path (N > SORTN only) ----------------
__global__ void geom_fb_kernel(const float* __restrict__ kpl,
                               const float* __restrict__ kpr,
                               const float* __restrict__ scores,
                               const float* __restrict__ Q, int B, int N) {
    int p = blockIdx.x * 256 + threadIdx.x;
    if (p >= B * N) return;
    int b = p / N;
    float pmx, pmz, hh, sq;
    bool valid = geom(kpl, kpr, scores, Q + (size_t)b * 16, p, pmx, pmz, hh, sq);
    g_h[p] = hh;
    g_valid[p] = valid ? 1 : 0;
    if (valid) {
        g_x[p] = pmx; g_z[p] = pmz; g_sq[p] = sq;
        atomicAdd(&g_validn[b], 1);
        atomicAdd(&g_Sh[b], hh);
    } else {
        g_x[p] = 0.f; g_z[p] = 0.f; g_sq[p] = 4e18f;
    }
}

__global__ void photo_fb_kernel(const float* __restrict__ lg,
                                const float* __restrict__ rg,
                                const float* __restrict__ kpl,
                                const float* __restrict__ kpr,
                                const float* __restrict__ scores,
                                int B, int N, int H, int W) {
    __shared__ float sacc[6];
    __shared__ int   scnt;
    int tid  = threadIdx.x;
    int warp = tid >> 5;
    int lane = tid & 31;
    if (tid < 6) sacc[tid] = 0.f;
    if (tid == 6) scnt = 0;
    __syncthreads();

    int total = B * N;
    int p = blockIdx.x * 8 + warp;
    if (p < total) {
        int b = p / N;
        float klx = __ldg(kpl + 2 * p),  kly = __ldg(kpl + 2 * p + 1);
        float krx = __ldg(kpr + 2 * p),  kry = __ldg(kpr + 2 * p + 1);
        float sc  = __ldg(scores + p);
        const float* L = lg + (size_t)b * H * W;
        const float* R = rg + (size_t)b * H * W;
        float tl0, tl1, tr0, tr1;
        sample_pair(L, klx, kly, W, H, lane, tl0, tl1);
        sample_pair(R, krx, kry, W, H, lane, tr0, tr1);
        int r = lane >> 2;
        float a = 0.f;
        if (r < 7) {
            a = fabsf(tl0 - tr0);
            if ((lane & 3) < 3) a += fabsf(tl1 - tr1);
        }
        #pragma unroll
        for (int o = 16; o > 0; o >>= 1)
            a += __shfl_down_sync(0xffffffffu, a, o);
        float cl = __shfl_sync(0xffffffffu, tl1, 13);
        float cr = __shfl_sync(0xffffffffu, tr1, 13);
        if (lane == 0) {
            float diffm = a / 49.f;
            float isb   = (cl > 0.02f) ? 1.f : 0.f;
            float w     = sc * isb;
            float ydiff = fabsf(kly - kry);
            atomicAdd(&sacc[0], sc);
            atomicAdd(&sacc[1], ydiff * sc);
            atomicAdd(&sacc[2], ydiff);
            atomicAdd(&sacc[3], w);
            atomicAdd(&sacc[4], diffm * w);
            atomicAdd(&sacc[5], smooth_l1f(cl, cr, 1.f) * w);
            if (sc > 0.1f) atomicAdd(&scnt, 1);
        }
    }
    __syncthreads();
    if (tid < 6) atomicAdd(&g_acc[tid], sacc[tid]);
    if (tid == 6 && scnt) atomicAdd(&g_cnt, scnt);
}

__global__ void knn_brute_kernel(int B, int N) {
    __shared__ float4 tile[256];
    __shared__ float  sls, ssl;
    int b = blockIdx.y;
    int n = blockIdx.x * blockDim.x + threadIdx.x;
    int rowBase = b * N;

    bool active = false;
    float xn = 0.f, zn = 0.f, sqn = 0.f, hn = 0.f;
    if (n < N) {
        int p = rowBase + n;
        active = (g_valid[p] != 0);
        xn = g_x[p]; zn = g_z[p]; sqn = g_sq[p]; hn = g_h[p];
    }
    float d2k[KK], hk[KK];
    #pragma unroll
    for (int k = 0; k < KK; k++) { d2k[k] = 3.4e38f; hk[k] = 0.f; }
    if (threadIdx.x == 0) { sls = 0.f; ssl = 0.f; }

    for (int basem = 0; basem < N; basem += 256) {
        int m = basem + threadIdx.x;
        if (m < N) {
            int q = rowBase + m;
            tile[threadIdx.x] = make_float4(g_x[q], g_z[q], g_h[q], g_sq[q]);
        }
        __syncthreads();
        int cnt = min(256, N - basem);
        if (active) {
            for (int j = 0; j < cnt; j++) {
                float4 v = tile[j];
                float d2 = sqn + v.w - 2.f * (xn * v.x + zn * v.y);
                INSERT6(d2, v.z);
            }
        }
        __syncthreads();
    }

    float ls = 0.f, pensum = 0.f;
    if (active) {
        float lm = (hk[1] + hk[2] + hk[3] + hk[4] + hk[5]) / 5.f;
        ls = smooth_l1f(hn, lm, 0.01f);
        #pragma unroll
        for (int k = 1; k < KK; k++) {
            float nd = fmaxf(sqrtf(fmaxf(d2k[k], 1e-12f)), 0.001f);
            float s  = fabsf(hk[k] - hn) / nd;
            pensum  += fmaxf(s - 0.4f, 0.f);
        }
    }
    #pragma unroll
    for (int o = 16; o > 0; o >>= 1) {
        ls     += __shfl_down_sync(0xffffffffu, ls, o);
        pensum += __shfl_down_sync(0xffffffffu, pensum, o);
    }
    if ((threadIdx.x & 31) == 0) { atomicAdd(&sls, ls); atomicAdd(&ssl, pensum); }
    __syncthreads();
    if (threadIdx.x == 0) { atomicAdd(&g_Sls[b], sls); atomicAdd(&g_Ssl[b], ssl); }
}

__global__ void final_kernel(float* __restrict__ out, int B, int N) {
    if (threadIdx.x < 32) do_finalize(out, B, N, threadIdx.x);
}

// ---------------- launch ----------------
extern "C" void kernel_launch(void* const* d_in, const int* in_sizes, int n_in,
                              void* d_out, int out_size) {
    const float* lg     = (const float*)d_in[0];
    const float* rg     = (const float*)d_in[1];
    const float* kpl    = (const float*)d_in[2];
    const float* kpr    = (const float*)d_in[3];
    const float* scores = (const float*)d_in[4];
    const float* Q      = (const float*)d_in[5];
    float* out = (float*)d_out;

    int B = in_sizes[5] / 16;
    int N = in_sizes[4] / B;
    int HW = in_sizes[0] / B;
    int W = 1280, H = HW / W;
    if (H * W != HW) { W = 1280; H = HW / W; }
    int total = B * N;
    int blocks1 = (total + 7) / 8;

    if (N <= SORTN && B <= MAXB) {
        geom_sort_kernel<<<B, 1024>>>(kpl, kpr, scores, Q, N);
        dim3 g2((N + 127) / 128, B);
        knn_window_kernel<<<g2, 256>>>(B, N);
        photo_flag_kernel<<<blocks1, 256>>>(out, lg, rg, kpl, kpr, scores,
                                            B, N, H, W, blocks1);
    } else {
        zero_kernel<<<1, 256>>>();
        geom_fb_kernel<<<(total + 255) / 256, 256>>>(kpl, kpr, scores, Q, B, N);
        photo_fb_kernel<<<blocks1, 256>>>(lg, rg, kpl, kpr, scores, B, N, H, W);
        dim3 g2((N + 255) / 256, B);
        knn_brute_kernel<<<g2, 256>>>(B, N);
        final_kernel<<<1, 32>>>(out, B, N);
    }
}

// round 15
// speedup vs baseline: 2.5140x; 2.5140x over previous
#include <cuda_runtime.h>
#include <cuda_bf16.h>
#include <math.h>

// ---------------- constants ----------------
#define KNN     5
#define KK      6        // K+1, self included then dropped
#define MAXPTS  65536
#define MAXB    64
#define SORTN   2048
#define WIN     64       // window half-width (64 validated; 48 = flag-rate cliff)
#define TILE    (128 + 4 * WIN + 2)

typedef unsigned long long ull;

// ---------------- device scratch ----------------
// (fallback path only)
__device__ float g_x[MAXPTS];
__device__ float g_z[MAXPTS];
__device__ float g_h[MAXPTS];
__device__ float g_sq[MAXPTS];
__device__ unsigned char g_valid[MAXPTS];

// sorted-by-z per batch, packed: (x, z, h, sq)
__device__ float4 gs_p[MAXB * SORTN];

__device__ int   g_nflag[MAXB];
__device__ int   g_flag[MAXB * SORTN];
__device__ float g_flagthr[MAXB * SORTN];   // certified 6th-NN d2 upper bound

__device__ int   g_validn[MAXB];
__device__ float g_Sh[MAXB];
__device__ float g_Sls[MAXB];
__device__ float g_Ssl[MAXB];

// [0]=sum(sc) [1]=sum(ydiff*sc) [2]=sum(ydiff) [3]=sum(w) [4]=sum(diff*w) [5]=sum(sl1*w)
__device__ float g_acc[8];
__device__ int   g_cnt;
__device__ int   g_done;

// ---------------- helpers ----------------
__device__ __forceinline__ float smooth_l1f(float x, float y, float beta) {
    float d = fabsf(x - y);
    return d < beta ? 0.5f * d * d / beta : d - 0.5f * beta;
}

__device__ __forceinline__ float bilinear_ref(const float* __restrict__ im,
                                              float x, float y, int W, int H) {
    x = fminf(fmaxf(x, 0.f), (float)(W - 1));
    y = fminf(fmaxf(y, 0.f), (float)(H - 1));
    float x0 = floorf(x), y0 = floorf(y);
    float fx = x - x0, fy = y - y0;
    int x0i = min(max((int)x0, 0), W - 1);
    int x1i = min(x0i + 1, W - 1);
    int y0i = min(max((int)y0, 0), H - 1);
    int y1i = min(y0i + 1, H - 1);
    float v00 = __ldg(im + (size_t)y0i * W + x0i);
    float v01 = __ldg(im + (size_t)y0i * W + x1i);
    float v10 = __ldg(im + (size_t)y1i * W + x0i);
    float v11 = __ldg(im + (size_t)y1i * W + x1i);
    float top = v00 * (1.f - fx) + v01 * fx;
    float bot = v10 * (1.f - fx) + v11 * fx;
    return top * (1.f - fy) + bot * fy;
}

__device__ __forceinline__ void sample_pair(const float* __restrict__ im,
                                            float cx, float cy, int W, int H,
                                            int lane, float& t0, float& t1) {
    float fix = floorf(cx), fiy = floorf(cy);
    float fx = cx - fix, fy = cy - fiy;
    int ix = (int)fix, iy = (int)fiy;
    int r = lane >> 2, cg = (lane & 3) << 1;
    bool fast = (ix >= 3) && (ix + 4 <= W - 1) && (iy >= 3) && (iy + 4 <= H - 1);
    if (fast) {
        const float* rp = im + (size_t)(iy - 3 + r) * W + (ix - 3 + cg);
        float w0 = __ldg(rp);
        float w1 = __ldg(rp + 1);
        float w2 = __shfl_down_sync(0xffffffffu, w0, 1);
        float ci0 = fmaf(fx, w1 - w0, w0);
        float ci1 = fmaf(fx, w2 - w1, w1);
        float cj0 = __shfl_down_sync(0xffffffffu, ci0, 4);
        float cj1 = __shfl_down_sync(0xffffffffu, ci1, 4);
        t0 = fmaf(fy, cj0 - ci0, ci0);
        t1 = fmaf(fy, cj1 - ci1, ci1);
    } else {
        t0 = bilinear_ref(im, cx + (float)(cg - 3), cy + (float)(r - 3), W, H);
        t1 = bilinear_ref(im, cx + (float)(cg - 2), cy + (float)(r - 3), W, H);
    }
}

// geometry for point p of batch b; returns valid
__device__ __forceinline__ bool geom(const float* __restrict__ kpl,
                                     const float* __restrict__ kpr,
                                     const float* __restrict__ scores,
                                     const float* __restrict__ Qb,
                                     int p, float& pmx, float& pmz,
                                     float& hh, float& sq) {
    float klx = __ldg(kpl + 2 * p), kly = __ldg(kpl + 2 * p + 1);
    float krx = __ldg(kpr + 2 * p);
    float sc  = __ldg(scores + p);
    float disp = klx - krx;
    float p0 = __ldg(Qb+0)  * klx + __ldg(Qb+1)  * kly + __ldg(Qb+2)  * disp + __ldg(Qb+3);
    float p1 = __ldg(Qb+4)  * klx + __ldg(Qb+5)  * kly + __ldg(Qb+6)  * disp + __ldg(Qb+7);
    float p2 = __ldg(Qb+8)  * klx + __ldg(Qb+9)  * kly + __ldg(Qb+10) * disp + __ldg(Qb+11);
    float p3 = __ldg(Qb+12) * klx + __ldg(Qb+13) * kly + __ldg(Qb+14) * disp + __ldg(Qb+15);
    float Wc = fmaxf(p3, 1e-6f);
    float X = p0 / Wc, Y = p1 / Wc, Z = p2 / Wc;
    bool valid = (Z > 100.f) && (Z < 30000.f) && (sc > 0.1f);
    pmx = X / 1000.f;
    hh  = Y / 1000.f;
    pmz = Z / 1000.f;
    sq  = pmx * pmx + pmz * pmz;
    return valid;
}

// sorted-insert (ascending) into static-indexed 6-lists
#define INSERT6(d2, hv)                                                     \
    if ((d2) < d2k[KK - 1]) {                                               \
        d2k[KK - 1] = (d2); hk[KK - 1] = (hv);                              \
        _Pragma("unroll")                                                   \
        for (int _k = KK - 1; _k > 0; _k--) {                               \
            if (d2k[_k] < d2k[_k - 1]) {                                    \
                float _td = d2k[_k]; d2k[_k] = d2k[_k-1]; d2k[_k-1] = _td;  \
                float _th = hk[_k];  hk[_k]  = hk[_k-1];  hk[_k-1]  = _th;  \
            }                                                               \
        }                                                                   \
    }

// warp-local compare-exchange for bitonic stage (k, j<=16) on packed keys
#define WARP_CEX(v, e, kk, jj)                                              \
    {                                                                       \
        ull _p = __shfl_xor_sync(0xffffffffu, (v), (jj));                   \
        bool _up = (((e) & (kk)) == 0);                                     \
        bool _keepmin = ((((e) & (jj)) == 0) == _up);                       \
        bool _takep = _keepmin ? (_p < (v)) : (_p > (v));                   \
        if (_takep) (v) = _p;                                               \
    }

// ---------------- kernel 0: zero accumulators (fallback path only) ---------
__global__ void zero_kernel() {
    int t = threadIdx.x;
    if (t < 8)   g_acc[t] = 0.f;
    if (t == 8)  g_cnt = 0;
    if (t == 9)  g_done = 0;
    if (t < MAXB) {
        g_validn[t] = 0;
        g_nflag[t]  = 0;
        g_Sls[t] = 0.f;
        g_Ssl[t] = 0.f;
        g_Sh[t]  = 0.f;
    }
}

// ---------------- kernel G: fused zero + geometry + hybrid z-sort ----------
__global__ void geom_sort_kernel(const float* __restrict__ kpl,
                                 const float* __restrict__ kpr,
                                 const float* __restrict__ scores,
                                 const float* __restrict__ Q, int N) {
    __shared__ ull  pack[SORTN];          // (z bits << 32) | idx
    __shared__ float sxv[SORTN], shv[SORTN], sqv[SORTN];
    __shared__ float warpH[32];
    __shared__ int   warpC[32];
    int b    = blockIdx.x;
    int tid  = threadIdx.x;   // 1024
    int w    = tid >> 5;
    int lane = tid & 31;
    int wb   = w * 64;        // warp owns elements [wb, wb+64)
    int e1   = wb + lane;
    int e2   = wb + 32 + lane;
    const float* Qb = Q + (size_t)b * 16;

    if (tid == 0) {
        g_nflag[b] = 0;
        g_Sls[b] = 0.f;
        g_Ssl[b] = 0.f;
    }
    if (b == 0) {
        if (tid < 8)  g_acc[tid] = 0.f;
        if (tid == 8) g_cnt = 0;
        if (tid == 9) g_done = 0;
    }

    // geometry for this thread's two owned elements, pack keys into registers
    int   cLoc = 0;
    float hLoc = 0.f;
    ull v1, v2;
    {
        int ee[2] = {e1, e2};
        ull vv[2];
        #pragma unroll
        for (int s = 0; s < 2; s++) {
            int i = ee[s];
            float key;
            if (i < N) {
                float pmx, pmz, hh, sq;
                bool valid = geom(kpl, kpr, scores, Qb, b * N + i, pmx, pmz, hh, sq);
                sxv[i] = pmx; shv[i] = hh; sqv[i] = sq;
                key = valid ? pmz : 1e30f;
                if (valid) { cLoc++; hLoc += hh; }
            } else {
                sxv[i] = 0.f; shv[i] = 0.f; sqv[i] = 4e18f;
                key = 3e30f;
            }
            vv[s] = ((ull)__float_as_uint(key) << 32) | (unsigned)i;
        }
        v1 = vv[0]; v2 = vv[1];
    }
    #pragma unroll
    for (int o = 16; o > 0; o >>= 1) {
        cLoc += __shfl_down_sync(0xffffffffu, cLoc, o);
        hLoc += __shfl_down_sync(0xffffffffu, hLoc, o);
    }
    if (lane == 0) { warpC[w] = cLoc; warpH[w] = hLoc; }

    // ---- bitonic sort, hybrid: levels k=2..32 fully in registers ----
    #pragma unroll
    for (int k = 2; k <= 32; k <<= 1) {
        for (int j = k >> 1; j > 0; j >>= 1) {
            WARP_CEX(v1, e1, k, j);
            WARP_CEX(v2, e2, k, j);
        }
    }
    pack[e1] = v1;
    pack[e2] = v2;
    __syncthreads();

    if (tid == 0) {
        int cT = 0; float hT = 0.f;
        #pragma unroll
        for (int wv = 0; wv < 32; wv++) { cT += warpC[wv]; hT += warpH[wv]; }
        g_validn[b] = cT;
        g_Sh[b]     = hT;
    }

    // ---- levels k=64..SORTN: j>=32 via smem, j<=16 tail in registers ----
    for (int k = 64; k <= SORTN; k <<= 1) {
        for (int j = k >> 1; j >= 32; j >>= 1) {
            #pragma unroll
            for (int it = 0; it < SORTN / 1024; it++) {
                int i = tid + it * 1024;
                int ixj = i ^ j;
                if (ixj > i) {
                    ull a = pack[i], c = pack[ixj];
                    bool up = ((i & k) == 0);
                    if ((a > c) == up) { pack[i] = c; pack[ixj] = a; }
                }
            }
            __syncthreads();
        }
        v1 = pack[e1];
        v2 = pack[e2];
        #pragma unroll
        for (int j = 16; j > 0; j >>= 1) {
            WARP_CEX(v1, e1, k, j);
            WARP_CEX(v2, e2, k, j);
        }
        pack[e1] = v1;
        pack[e2] = v2;
        __syncthreads();
    }

    #pragma unroll
    for (int it = 0; it < SORTN / 1024; it++) {
        int i = tid + it * 1024;
        ull v = pack[i];
        int idx = (int)(v & 0xffffffffu);
        float zz = __uint_as_float((unsigned)(v >> 32));
        gs_p[b * SORTN + i] = make_float4(sxv[idx], zz, shv[idx], sqv[idx]);
    }
}

// ---------------- kernel P: photo only (one warp per keypoint) ----------------
__global__ void photo_kernel(const float* __restrict__ lg,
                             const float* __restrict__ rg,
                             const float* __restrict__ kpl,
                             const float* __restrict__ kpr,
                             const float* __restrict__ scores,
                             int B, int N, int H, int W) {
    __shared__ float sacc[6];
    __shared__ int   scnt;
    int tid  = threadIdx.x;
    int warp = tid >> 5;
    int lane = tid & 31;
    if (tid < 6) sacc[tid] = 0.f;
    if (tid == 6) scnt = 0;
    __syncthreads();

    int total = B * N;
    int p = blockIdx.x * 8 + warp;
    if (p < total) {
        int b = p / N;
        float klx = __ldg(kpl + 2 * p),  kly = __ldg(kpl + 2 * p + 1);
        float krx = __ldg(kpr + 2 * p),  kry = __ldg(kpr + 2 * p + 1);
        float sc  = __ldg(scores + p);

        const float* L = lg + (size_t)b * H * W;
        const float* R = rg + (size_t)b * H * W;
        float tl0, tl1, tr0, tr1;
        sample_pair(L, klx, kly, W, H, lane, tl0, tl1);
        sample_pair(R, krx, kry, W, H, lane, tr0, tr1);

        int r = lane >> 2;
        float a = 0.f;
        if (r < 7) {
            a = fabsf(tl0 - tr0);
            if ((lane & 3) < 3) a += fabsf(tl1 - tr1);
        }
        #pragma unroll
        for (int o = 16; o > 0; o >>= 1)
            a += __shfl_down_sync(0xffffffffu, a, o);

        float cl = __shfl_sync(0xffffffffu, tl1, 13);
        float cr = __shfl_sync(0xffffffffu, tr1, 13);

        if (lane == 0) {
            float diffm = a / 49.f;
            float isb   = (cl > 0.02f) ? 1.f : 0.f;
            float w     = sc * isb;
            float ydiff = fabsf(kly - kry);
            atomicAdd(&sacc[0], sc);
            atomicAdd(&sacc[1], ydiff * sc);
            atomicAdd(&sacc[2], ydiff);
            atomicAdd(&sacc[3], w);
            atomicAdd(&sacc[4], diffm * w);
            atomicAdd(&sacc[5], smooth_l1f(cl, cr, 1.f) * w);
            if (sc > 0.1f) atomicAdd(&scnt, 1);
        }
    }
    __syncthreads();
    if (tid < 6) atomicAdd(&g_acc[tid], sacc[tid]);
    if (tid == 6 && scnt) atomicAdd(&g_cnt, scnt);
}

// ---------------- kernel 2b: split-window 6-NN over z-sorted VALID prefix ----
__global__ void knn_window_kernel(int B, int N) {
    __shared__ float sx[TILE], sz[TILE], sh[TILE], sq[TILE];
    __shared__ float lists[256][2 * KK];
    __shared__ float sls, ssl;
    int b    = blockIdx.y;
    int tid  = threadIdx.x;      // 256
    int t    = tid & 127;
    int half = tid >> 7;
    int blockStart = blockIdx.x * 128;
    int n    = blockStart + t;
    int base = b * SORTN;

    int nv = g_validn[b];
    int tl = max(0, blockStart - 2 * WIN - 1);
    int th = min(nv, blockStart + 128 + 2 * WIN + 1);
    int cnt = max(0, th - tl);
    for (int i = tid; i < cnt; i += 256) {
        float4 v = gs_p[base + tl + i];
        sx[i] = v.x; sz[i] = v.y; sh[i] = v.z; sq[i] = v.w;
    }
    if (tid == 0) { sls = 0.f; ssl = 0.f; }
    __syncthreads();

    bool active = (n < nv);

    float d2k[KK], hk[KK];
    #pragma unroll
    for (int k = 0; k < KK; k++) { d2k[k] = 3.4e38f; hk[k] = 0.f; }

    int lo = 0, hi = 0;
    float xn = 0.f, zn = 0.f, hn = 0.f, sqn = 0.f;
    if (active) {
        xn = sx[n - tl]; zn = sz[n - tl]; hn = sh[n - tl]; sqn = sq[n - tl];

        lo = n - WIN;
        hi = n + WIN;
        if (lo < 0)  { hi -= lo; lo = 0; }
        if (hi > nv) { lo -= (hi - nv); hi = nv; if (lo < 0) lo = 0; }

        int mid = (lo + hi) >> 1;
        int beg = half ? mid : lo;
        int end = half ? hi  : mid;

        for (int j = beg; j < end; j++) {
            int ji = j - tl;
            float d2 = sqn + sq[ji] - 2.f * (xn * sx[ji] + zn * sz[ji]);
            INSERT6(d2, sh[ji]);
        }
    }
    #pragma unroll
    for (int k = 0; k < KK; k++) {
        lists[tid][k]      = d2k[k];
        lists[tid][KK + k] = hk[k];
    }
    __syncthreads();

    float ls = 0.f, pensum = 0.f;
    if (tid < 128 && active) {
        const float* pa = lists[tid];
        const float* pb = lists[tid + 128];
        float md[KK], mh[KK];
        int ia = 0, ib = 0;
        #pragma unroll
        for (int k = 0; k < KK; k++) {
            float da = pa[ia], db = pb[ib];
            bool ta = (da <= db);
            md[k] = ta ? da : db;
            mh[k] = ta ? pa[KK + ia] : pb[KK + ib];
            ia += ta ? 1 : 0;
            ib += ta ? 0 : 1;
        }

        float thr = md[KK - 1] * 1.0001f + 1e-9f;
        bool bad = false;
        if (lo > 0)  { float dz = zn - sz[lo - 1 - tl]; if (dz * dz <= thr) bad = true; }
        if (hi < nv) { float dz = sz[hi - tl] - zn;     if (dz * dz <= thr) bad = true; }

        if (bad) {
            int slot = atomicAdd(&g_nflag[b], 1);
            g_flag[base + slot]    = n;
            g_flagthr[base + slot] = thr;
        } else {
            float lm = (mh[1] + mh[2] + mh[3] + mh[4] + mh[5]) / 5.f;
            ls = smooth_l1f(hn, lm, 0.01f);
            #pragma unroll
            for (int k = 1; k < KK; k++) {
                float nd = fmaxf(sqrtf(fmaxf(md[k], 1e-12f)), 0.001f);
                float s  = fabsf(mh[k] - hn) / nd;
                pensum  += fmaxf(s - 0.4f, 0.f);
            }
        }
    }

    #pragma unroll
    for (int o = 16; o > 0; o >>= 1) {
        ls     += __shfl_down_sync(0xffffffffu, ls, o);
        pensum += __shfl_down_sync(0xffffffffu, pensum, o);
    }
    if ((tid & 31) == 0) {
        atomicAdd(&sls, ls);
        atomicAdd(&ssl, pensum);
    }
    __syncthreads();
    if (tid == 0) {
        atomicAdd(&g_Sls[b], sls);
        atomicAdd(&g_Ssl[b], ssl);
    }
}

// ---------------- finalize (device function, run by one warp) ----------------
__device__ __forceinline__ void do_finalize(float* __restrict__ out, int B, int N, int t) {
    float s_ls = 0.f, s_sl = 0.f, s_lz = 0.f, s_ok = 0.f;
    for (int b = t; b < B; b += 32) {
        int nvi  = g_validn[b];
        float nv = (float)max(nvi, 1);
        float ok = (nvi >= 10) ? 1.f : 0.f;
        s_ls += ok * (g_Sls[b] / nv);
        s_sl += ok * (g_Ssl[b] / (nv * (float)KNN));
        s_lz += ok * fabsf(g_Sh[b] / nv);
        s_ok += ok;
    }
    float accv = (t < 6) ? g_acc[t] : 0.f;
    int   cntv = g_cnt;
    #pragma unroll
    for (int o = 16; o > 0; o >>= 1) {
        s_ls += __shfl_down_sync(0xffffffffu, s_ls, o);
        s_sl += __shfl_down_sync(0xffffffffu, s_sl, o);
        s_lz += __shfl_down_sync(0xffffffffu, s_lz, o);
        s_ok += __shfl_down_sync(0xffffffffu, s_ok, o);
    }
    float a0 = __shfl_sync(0xffffffffu, accv, 0);
    float a1 = __shfl_sync(0xffffffffu, accv, 1);
    float a2 = __shfl_sync(0xffffffffu, accv, 2);
    float a3 = __shfl_sync(0xffffffffu, accv, 3);
    float a4 = __shfl_sync(0xffffffffu, accv, 4);
    float a5 = __shfl_sync(0xffffffffu, accv, 5);
    if (t == 0) {
        float l_epi = (a0 > 0.0001f) ? (a1 / fmaxf(a0, 1e-12f))
                                     : (a2 / (float)(B * N));
        float safe = fmaxf(a3, 1e-12f);
        float l_masked    = (a3 > 0.0001f) ? (a4 / safe) : 0.f;
        float l_intensity = (a3 > 0.0001f) ? (a5 / safe) : 0.f;

        float nb = fmaxf(s_ok, 1.f);
        bool gate = (cntv >= 10) && (s_ok > 0.f);

        out[0] = l_masked + l_intensity;
        out[1] = l_epi;
        out[2] = gate ? (s_ls / nb) : 0.f;
        out[3] = gate ? (s_sl / nb) : 0.f;
        out[4] = gate ? (s_lz / nb) : 0.f;
    }
}

// ---------------- kernel 2c: flagged-point z-bounded exact scan + finalize ---
#define FLAGBX 16
__global__ void knn_flag_kernel(float* __restrict__ out, int B, int N, int totalBlocks) {
    __shared__ float sls, ssl;
    __shared__ int isLast;
    int b    = blockIdx.y;
    int tid  = threadIdx.x;        // 256 = 8 warps
    int lane = tid & 31;
    int wIdx = blockIdx.x * 8 + (tid >> 5);
    int warpsPerBatch = gridDim.x * 8;
    int base = b * SORTN;
    int nf = g_nflag[b];
    int nv = g_validn[b];
    const float4* P = gs_p + base;

    if (tid == 0) { sls = 0.f; ssl = 0.f; }
    __syncthreads();

    float lsAcc = 0.f, penAcc = 0.f;
    for (int f = wIdx; f < nf; f += warpsPerBatch) {
        int n = g_flag[base + f];
        float thr0 = g_flagthr[base + f];
        float4 me = __ldg(&P[n]);
        float xn = me.x, zn = me.y, hn = me.z, sqn = me.w;

        float dzmax = sqrtf(thr0);
        float zLo = zn - dzmax, zHi = zn + dzmax;
        int lo = 0, hiB = nv;
        while (lo < hiB) { int m = (lo + hiB) >> 1; if (__ldg(&P[m]).y < zLo) lo = m + 1; else hiB = m; }
        int jlo = lo;
        lo = jlo; hiB = nv;
        while (lo < hiB) { int m = (lo + hiB) >> 1; if (__ldg(&P[m]).y <= zHi) lo = m + 1; else hiB = m; }
        int jhi = lo;

        float d2k[KK], hk[KK];
        #pragma unroll
        for (int k = 0; k < KK; k++) { d2k[k] = 3.4e38f; hk[k] = 0.f; }

        int j = jlo + lane;
        for (; j + 96 < jhi; j += 128) {
            float4 v0 = __ldg(&P[j]);
            float4 v1 = __ldg(&P[j + 32]);
            float4 v2 = __ldg(&P[j + 64]);
            float4 v3 = __ldg(&P[j + 96]);
            float d0 = sqn + v0.w - 2.f * (xn * v0.x + zn * v0.y);
            float d1 = sqn + v1.w - 2.f * (xn * v1.x + zn * v1.y);
            float d2_ = sqn + v2.w - 2.f * (xn * v2.x + zn * v2.y);
            float d3 = sqn + v3.w - 2.f * (xn * v3.x + zn * v3.y);
            INSERT6(d0, v0.z);
            INSERT6(d1, v1.z);
            INSERT6(d2_, v2.z);
            INSERT6(d3, v3.z);
        }
        for (; j < jhi; j += 32) {
            float4 v = __ldg(&P[j]);
            float d2 = sqn + v.w - 2.f * (xn * v.x + zn * v.y);
            INSERT6(d2, v.z);
        }

        float md[KK], mh[KK];
        #pragma unroll
        for (int r = 0; r < KK; r++) {
            float v  = d2k[0];
            float mv = v;
            #pragma unroll
            for (int o = 16; o > 0; o >>= 1)
                mv = fminf(mv, __shfl_xor_sync(0xffffffffu, mv, o));
            unsigned msk = __ballot_sync(0xffffffffu, v == mv);
            int src = __ffs(msk) - 1;
            float hh0 = hk[0];
            float mhh = __shfl_sync(0xffffffffu, hh0, src);
            if (lane == src) {
                #pragma unroll
                for (int k = 0; k < KK - 1; k++) { d2k[k] = d2k[k + 1]; hk[k] = hk[k + 1]; }
                d2k[KK - 1] = 3.4e38f; hk[KK - 1] = 0.f;
            }
            md[r] = mv; mh[r] = mhh;
        }

        if (lane == 0) {
            float lm = (mh[1] + mh[2] + mh[3] + mh[4] + mh[5]) / 5.f;
            lsAcc += smooth_l1f(hn, lm, 0.01f);
            #pragma unroll
            for (int k = 1; k < KK; k++) {
                float nd = fmaxf(sqrtf(fmaxf(md[k], 1e-12f)), 0.001f);
                float s  = fabsf(mh[k] - hn) / nd;
                penAcc  += fmaxf(s - 0.4f, 0.f);
            }
        }
    }
    if (lane == 0 && (lsAcc != 0.f || penAcc != 0.f)) {
        atomicAdd(&sls, lsAcc);
        atomicAdd(&ssl, penAcc);
    }
    __syncthreads();
    if (tid == 0) {
        if (sls != 0.f || ssl != 0.f) {
            atomicAdd(&g_Sls[b], sls);
            atomicAdd(&g_Ssl[b], ssl);
        }
        __threadfence();
        int v = atomicAdd(&g_done, 1);
        isLast = (v == totalBlocks - 1) ? 1 : 0;
    }
    __syncthreads();
    if (isLast && tid < 32) {
        do_finalize(out, B, N, tid);
    }
}

// ---------------- fallback path (N > SORTN only) ----------------
__global__ void geom_fb_kernel(const float* __restrict__ kpl,
                               const float* __restrict__ kpr,
                               const float* __restrict__ scores,
                               const float* __restrict__ Q, int B, int N) {
    int p = blockIdx.x * 256 + threadIdx.x;
    if (p >= B * N) return;
    int b = p / N;
    float pmx, pmz, hh, sq;
    bool valid = geom(kpl, kpr, scores, Q + (size_t)b * 16, p, pmx, pmz, hh, sq);
    g_h[p] = hh;
    g_valid[p] = valid ? 1 : 0;
    if (valid) {
        g_x[p] = pmx; g_z[p] = pmz; g_sq[p] = sq;
        atomicAdd(&g_validn[b], 1);
        atomicAdd(&g_Sh[b], hh);
    } else {
        g_x[p] = 0.f; g_z[p] = 0.f; g_sq[p] = 4e18f;
    }
}

__global__ void knn_brute_kernel(int B, int N) {
    __shared__ float4 tile[256];
    __shared__ float  sls, ssl;
    int b = blockIdx.y;
    int n = blockIdx.x * blockDim.x + threadIdx.x;
    int rowBase = b * N;

    bool active = false;
    float xn = 0.f, zn = 0.f, sqn = 0.f, hn = 0.f;
    if (n < N) {
        int p = rowBase + n;
        active = (g_valid[p] != 0);
        xn = g_x[p]; zn = g_z[p]; sqn = g_sq[p]; hn = g_h[p];
    }
    float d2k[KK], hk[KK];
    #pragma unroll
    for (int k = 0; k < KK; k++) { d2k[k] = 3.4e38f; hk[k] = 0.f; }
    if (threadIdx.x == 0) { sls = 0.f; ssl = 0.f; }

    for (int basem = 0; basem < N; basem += 256) {
        int m = basem + threadIdx.x;
        if (m < N) {
            int q = rowBase + m;
            tile[threadIdx.x] = make_float4(g_x[q], g_z[q], g_h[q], g_sq[q]);
        }
        __syncthreads();
        int cnt = min(256, N - basem);
        if (active) {
            for (int j = 0; j < cnt; j++) {
                float4 v = tile[j];
                float d2 = sqn + v.w - 2.f * (xn * v.x + zn * v.y);
                INSERT6(d2, v.z);
            }
        }
        __syncthreads();
    }

    float ls = 0.f, pensum = 0.f;
    if (active) {
        float lm = (hk[1] + hk[2] + hk[3] + hk[4] + hk[5]) / 5.f;
        ls = smooth_l1f(hn, lm, 0.01f);
        #pragma unroll
        for (int k = 1; k < KK; k++) {
            float nd = fmaxf(sqrtf(fmaxf(d2k[k], 1e-12f)), 0.001f);
            float s  = fabsf(hk[k] - hn) / nd;
            pensum  += fmaxf(s - 0.4f, 0.f);
        }
    }
    #pragma unroll
    for (int o = 16; o > 0; o >>= 1) {
        ls     += __shfl_down_sync(0xffffffffu, ls, o);
        pensum += __shfl_down_sync(0xffffffffu, pensum, o);
    }
    if ((threadIdx.x & 31) == 0) { atomicAdd(&sls, ls); atomicAdd(&ssl, pensum); }
    __syncthreads();
    if (threadIdx.x == 0) { atomicAdd(&g_Sls[b], sls); atomicAdd(&g_Ssl[b], ssl); }
}

__global__ void final_kernel(float* __restrict__ out, int B, int N) {
    if (threadIdx.x < 32) do_finalize(out, B, N, threadIdx.x);
}

// ---------------- launch ----------------
extern "C" void kernel_launch(void* const* d_in, const int* in_sizes, int n_in,
                              void* d_out, int out_size) {
    const float* lg     = (const float*)d_in[0];
    const float* rg     = (const float*)d_in[1];
    const float* kpl    = (const float*)d_in[2];
    const float* kpr    = (const float*)d_in[3];
    const float* scores = (const float*)d_in[4];
    const float* Q      = (const float*)d_in[5];
    float* out = (float*)d_out;

    int B = in_sizes[5] / 16;
    int N = in_sizes[4] / B;
    int HW = in_sizes[0] / B;
    int W = 1280, H = HW / W;
    if (H * W != HW) { W = 1280; H = HW / W; }
    int total = B * N;
    int blocks1 = (total + 7) / 8;

    if (N <= SORTN && B <= MAXB) {
        geom_sort_kernel<<<B, 1024>>>(kpl, kpr, scores, Q, N);
        photo_kernel<<<blocks1, 256>>>(lg, rg, kpl, kpr, scores, B, N, H, W);
        dim3 g2((N + 127) / 128, B);
        knn_window_kernel<<<g2, 256>>>(B, N);
        dim3 g3(FLAGBX, B);
        knn_flag_kernel<<<g3, 256>>>(out, B, N, FLAGBX * B);
    } else {
        zero_kernel<<<1, 256>>>();
        geom_fb_kernel<<<(total + 255) / 256, 256>>>(kpl, kpr, scores, Q, B, N);
        photo_kernel<<<blocks1, 256>>>(lg, rg, kpl, kpr, scores, B, N, H, W);
        dim3 g2((N + 255) / 256, B);
        knn_brute_kernel<<<g2, 256>>>(B, N);
        final_kernel<<<1, 32>>>(out, B, N);
    }
}

// round 16
// speedup vs baseline: 2.7282x; 1.0852x over previous
#include <cuda_runtime.h>
#include <cuda_bf16.h>
#include <math.h>

// ---------------- constants ----------------
#define KNN     5
#define KK      6        // K+1, self included then dropped
#define MAXPTS  65536
#define MAXB    64
#define SORTN   2048
#define WIN     64       // window half-width (64 validated; 48 = flag-rate cliff)
#define TILE    (128 + 4 * WIN + 2)

typedef unsigned long long ull;

// ---------------- device scratch ----------------
// (fallback path only)
__device__ float g_x[MAXPTS];
__device__ float g_z[MAXPTS];
__device__ float g_h[MAXPTS];
__device__ float g_sq[MAXPTS];
__device__ unsigned char g_valid[MAXPTS];

// sorted-by-z per batch, packed: (x, z, h, sq)
__device__ float4 gs_p[MAXB * SORTN];

__device__ int   g_nflag[MAXB];
__device__ int   g_flag[MAXB * SORTN];
__device__ float g_flagthr[MAXB * SORTN];   // certified 6th-NN d2 upper bound

__device__ int   g_validn[MAXB];
__device__ float g_Sh[MAXB];
__device__ float g_Sls[MAXB];
__device__ float g_Ssl[MAXB];

// [0]=sum(sc) [1]=sum(ydiff*sc) [2]=sum(ydiff) [3]=sum(w) [4]=sum(diff*w) [5]=sum(sl1*w)
__device__ float g_acc[8];
__device__ int   g_cnt;
__device__ int   g_done;

// ---------------- helpers ----------------
__device__ __forceinline__ float smooth_l1f(float x, float y, float beta) {
    float d = fabsf(x - y);
    return d < beta ? 0.5f * d * d / beta : d - 0.5f * beta;
}

__device__ __forceinline__ float bilinear_ref(const float* __restrict__ im,
                                              float x, float y, int W, int H) {
    x = fminf(fmaxf(x, 0.f), (float)(W - 1));
    y = fminf(fmaxf(y, 0.f), (float)(H - 1));
    float x0 = floorf(x), y0 = floorf(y);
    float fx = x - x0, fy = y - y0;
    int x0i = min(max((int)x0, 0), W - 1);
    int x1i = min(x0i + 1, W - 1);
    int y0i = min(max((int)y0, 0), H - 1);
    int y1i = min(y0i + 1, H - 1);
    float v00 = __ldg(im + (size_t)y0i * W + x0i);
    float v01 = __ldg(im + (size_t)y0i * W + x1i);
    float v10 = __ldg(im + (size_t)y1i * W + x0i);
    float v11 = __ldg(im + (size_t)y1i * W + x1i);
    float top = v00 * (1.f - fx) + v01 * fx;
    float bot = v10 * (1.f - fx) + v11 * fx;
    return top * (1.f - fy) + bot * fy;
}

__device__ __forceinline__ void sample_pair(const float* __restrict__ im,
                                            float cx, float cy, int W, int H,
                                            int lane, float& t0, float& t1) {
    float fix = floorf(cx), fiy = floorf(cy);
    float fx = cx - fix, fy = cy - fiy;
    int ix = (int)fix, iy = (int)fiy;
    int r = lane >> 2, cg = (lane & 3) << 1;
    bool fast = (ix >= 3) && (ix + 4 <= W - 1) && (iy >= 3) && (iy + 4 <= H - 1);
    if (fast) {
        const float* rp = im + (size_t)(iy - 3 + r) * W + (ix - 3 + cg);
        float w0 = __ldg(rp);
        float w1 = __ldg(rp + 1);
        float w2 = __shfl_down_sync(0xffffffffu, w0, 1);
        float ci0 = fmaf(fx, w1 - w0, w0);
        float ci1 = fmaf(fx, w2 - w1, w1);
        float cj0 = __shfl_down_sync(0xffffffffu, ci0, 4);
        float cj1 = __shfl_down_sync(0xffffffffu, ci1, 4);
        t0 = fmaf(fy, cj0 - ci0, ci0);
        t1 = fmaf(fy, cj1 - ci1, ci1);
    } else {
        t0 = bilinear_ref(im, cx + (float)(cg - 3), cy + (float)(r - 3), W, H);
        t1 = bilinear_ref(im, cx + (float)(cg - 2), cy + (float)(r - 3), W, H);
    }
}

// geometry for point p of batch b; returns valid
__device__ __forceinline__ bool geom(const float* __restrict__ kpl,
                                     const float* __restrict__ kpr,
                                     const float* __restrict__ scores,
                                     const float* __restrict__ Qb,
                                     int p, float& pmx, float& pmz,
                                     float& hh, float& sq) {
    float klx = __ldg(kpl + 2 * p), kly = __ldg(kpl + 2 * p + 1);
    float krx = __ldg(kpr + 2 * p);
    float sc  = __ldg(scores + p);
    float disp = klx - krx;
    float p0 = __ldg(Qb+0)  * klx + __ldg(Qb+1)  * kly + __ldg(Qb+2)  * disp + __ldg(Qb+3);
    float p1 = __ldg(Qb+4)  * klx + __ldg(Qb+5)  * kly + __ldg(Qb+6)  * disp + __ldg(Qb+7);
    float p2 = __ldg(Qb+8)  * klx + __ldg(Qb+9)  * kly + __ldg(Qb+10) * disp + __ldg(Qb+11);
    float p3 = __ldg(Qb+12) * klx + __ldg(Qb+13) * kly + __ldg(Qb+14) * disp + __ldg(Qb+15);
    float Wc = fmaxf(p3, 1e-6f);
    float X = p0 / Wc, Y = p1 / Wc, Z = p2 / Wc;
    bool valid = (Z > 100.f) && (Z < 30000.f) && (sc > 0.1f);
    pmx = X / 1000.f;
    hh  = Y / 1000.f;
    pmz = Z / 1000.f;
    sq  = pmx * pmx + pmz * pmz;
    return valid;
}

// sorted-insert (ascending) into static-indexed 6-lists
#define INSERT6(d2, hv)                                                     \
    if ((d2) < d2k[KK - 1]) {                                               \
        d2k[KK - 1] = (d2); hk[KK - 1] = (hv);                              \
        _Pragma("unroll")                                                   \
        for (int _k = KK - 1; _k > 0; _k--) {                               \
            if (d2k[_k] < d2k[_k - 1]) {                                    \
                float _td = d2k[_k]; d2k[_k] = d2k[_k-1]; d2k[_k-1] = _td;  \
                float _th = hk[_k];  hk[_k]  = hk[_k-1];  hk[_k-1]  = _th;  \
            }                                                               \
        }                                                                   \
    }

// warp-local compare-exchange for bitonic stage (k, j<=16) on packed keys
#define WARP_CEX(v, e, kk, jj)                                              \
    {                                                                       \
        ull _p = __shfl_xor_sync(0xffffffffu, (v), (jj));                   \
        bool _up = (((e) & (kk)) == 0);                                     \
        bool _keepmin = ((((e) & (jj)) == 0) == _up);                       \
        bool _takep = _keepmin ? (_p < (v)) : (_p > (v));                   \
        if (_takep) (v) = _p;                                               \
    }

// ---------------- kernel 0: zero accumulators (fallback path only) ---------
__global__ void zero_kernel() {
    int t = threadIdx.x;
    if (t < 8)   g_acc[t] = 0.f;
    if (t == 8)  g_cnt = 0;
    if (t == 9)  g_done = 0;
    if (t < MAXB) {
        g_validn[t] = 0;
        g_nflag[t]  = 0;
        g_Sls[t] = 0.f;
        g_Ssl[t] = 0.f;
        g_Sh[t]  = 0.f;
    }
}

// ---------------- kernel G: fused zero + geometry + hybrid z-sort ----------
__global__ void geom_sort_kernel(const float* __restrict__ kpl,
                                 const float* __restrict__ kpr,
                                 const float* __restrict__ scores,
                                 const float* __restrict__ Q, int N) {
    __shared__ ull  pack[SORTN];          // (z bits << 32) | idx
    __shared__ float sxv[SORTN], shv[SORTN], sqv[SORTN];
    __shared__ float warpH[32];
    __shared__ int   warpC[32];
    int b    = blockIdx.x;
    int tid  = threadIdx.x;   // 1024
    int w    = tid >> 5;
    int lane = tid & 31;
    int wb   = w * 64;        // warp owns elements [wb, wb+64)
    int e1   = wb + lane;
    int e2   = wb + 32 + lane;
    const float* Qb = Q + (size_t)b * 16;

    if (tid == 0) {
        g_nflag[b] = 0;
        g_Sls[b] = 0.f;
        g_Ssl[b] = 0.f;
    }
    if (b == 0) {
        if (tid < 8)  g_acc[tid] = 0.f;
        if (tid == 8) g_cnt = 0;
        if (tid == 9) g_done = 0;
    }

    int   cLoc = 0;
    float hLoc = 0.f;
    ull v1, v2;
    {
        int ee[2] = {e1, e2};
        ull vv[2];
        #pragma unroll
        for (int s = 0; s < 2; s++) {
            int i = ee[s];
            float key;
            if (i < N) {
                float pmx, pmz, hh, sq;
                bool valid = geom(kpl, kpr, scores, Qb, b * N + i, pmx, pmz, hh, sq);
                sxv[i] = pmx; shv[i] = hh; sqv[i] = sq;
                key = valid ? pmz : 1e30f;
                if (valid) { cLoc++; hLoc += hh; }
            } else {
                sxv[i] = 0.f; shv[i] = 0.f; sqv[i] = 4e18f;
                key = 3e30f;
            }
            vv[s] = ((ull)__float_as_uint(key) << 32) | (unsigned)i;
        }
        v1 = vv[0]; v2 = vv[1];
    }
    #pragma unroll
    for (int o = 16; o > 0; o >>= 1) {
        cLoc += __shfl_down_sync(0xffffffffu, cLoc, o);
        hLoc += __shfl_down_sync(0xffffffffu, hLoc, o);
    }
    if (lane == 0) { warpC[w] = cLoc; warpH[w] = hLoc; }

    // levels k=2..32 fully in registers
    #pragma unroll
    for (int k = 2; k <= 32; k <<= 1) {
        for (int j = k >> 1; j > 0; j >>= 1) {
            WARP_CEX(v1, e1, k, j);
            WARP_CEX(v2, e2, k, j);
        }
    }
    pack[e1] = v1;
    pack[e2] = v2;
    __syncthreads();

    if (tid == 0) {
        int cT = 0; float hT = 0.f;
        #pragma unroll
        for (int wv = 0; wv < 32; wv++) { cT += warpC[wv]; hT += warpH[wv]; }
        g_validn[b] = cT;
        g_Sh[b]     = hT;
    }

    // levels k=64..SORTN: j>=32 via smem, j<=16 tail in registers
    for (int k = 64; k <= SORTN; k <<= 1) {
        for (int j = k >> 1; j >= 32; j >>= 1) {
            #pragma unroll
            for (int it = 0; it < SORTN / 1024; it++) {
                int i = tid + it * 1024;
                int ixj = i ^ j;
                if (ixj > i) {
                    ull a = pack[i], c = pack[ixj];
                    bool up = ((i & k) == 0);
                    if ((a > c) == up) { pack[i] = c; pack[ixj] = a; }
                }
            }
            __syncthreads();
        }
        v1 = pack[e1];
        v2 = pack[e2];
        #pragma unroll
        for (int j = 16; j > 0; j >>= 1) {
            WARP_CEX(v1, e1, k, j);
            WARP_CEX(v2, e2, k, j);
        }
        pack[e1] = v1;
        pack[e2] = v2;
        __syncthreads();
    }

    #pragma unroll
    for (int it = 0; it < SORTN / 1024; it++) {
        int i = tid + it * 1024;
        ull v = pack[i];
        int idx = (int)(v & 0xffffffffu);
        float zz = __uint_as_float((unsigned)(v >> 32));
        gs_p[b * SORTN + i] = make_float4(sxv[idx], zz, shv[idx], sqv[idx]);
    }
}

// ---------------- kernel WP: window blocks + photo blocks in ONE launch ----
// blocks [0, windowBlocks): window 6-NN (exact R15 body), bid -> (b, wx)
// blocks [windowBlocks, +): photo (exact R15 body)
__global__ void window_photo_kernel(const float* __restrict__ lg,
                                    const float* __restrict__ rg,
                                    const float* __restrict__ kpl,
                                    const float* __restrict__ kpr,
                                    const float* __restrict__ scores,
                                    int B, int N, int H, int W,
                                    int WX, int windowBlocks) {
    __shared__ float sx[TILE], sz[TILE], sh[TILE], sq[TILE];
    __shared__ float lists[256][2 * KK];
    __shared__ float sred[8];
    __shared__ int   sint;
    int tid  = threadIdx.x;      // 256

    if ((int)blockIdx.x < windowBlocks) {
        // ================= WINDOW BLOCK =================
        int b    = blockIdx.x / WX;
        int wx   = blockIdx.x % WX;
        int t    = tid & 127;
        int half = tid >> 7;
        int blockStart = wx * 128;
        int n    = blockStart + t;
        int base = b * SORTN;

        int nv = g_validn[b];
        int tl = max(0, blockStart - 2 * WIN - 1);
        int th = min(nv, blockStart + 128 + 2 * WIN + 1);
        int cnt = max(0, th - tl);
        for (int i = tid; i < cnt; i += 256) {
            float4 v = gs_p[base + tl + i];
            sx[i] = v.x; sz[i] = v.y; sh[i] = v.z; sq[i] = v.w;
        }
        if (tid == 0) { sred[0] = 0.f; sred[1] = 0.f; }
        __syncthreads();

        bool active = (n < nv);

        float d2k[KK], hk[KK];
        #pragma unroll
        for (int k = 0; k < KK; k++) { d2k[k] = 3.4e38f; hk[k] = 0.f; }

        int lo = 0, hi = 0;
        float xn = 0.f, zn = 0.f, hn = 0.f, sqn = 0.f;
        if (active) {
            xn = sx[n - tl]; zn = sz[n - tl]; hn = sh[n - tl]; sqn = sq[n - tl];

            lo = n - WIN;
            hi = n + WIN;
            if (lo < 0)  { hi -= lo; lo = 0; }
            if (hi > nv) { lo -= (hi - nv); hi = nv; if (lo < 0) lo = 0; }

            int mid = (lo + hi) >> 1;
            int beg = half ? mid : lo;
            int end = half ? hi  : mid;

            for (int j = beg; j < end; j++) {
                int ji = j - tl;
                float d2 = sqn + sq[ji] - 2.f * (xn * sx[ji] + zn * sz[ji]);
                INSERT6(d2, sh[ji]);
            }
        }
        #pragma unroll
        for (int k = 0; k < KK; k++) {
            lists[tid][k]      = d2k[k];
            lists[tid][KK + k] = hk[k];
        }
        __syncthreads();

        float ls = 0.f, pensum = 0.f;
        if (tid < 128 && active) {
            const float* pa = lists[tid];
            const float* pb = lists[tid + 128];
            float md[KK], mh[KK];
            int ia = 0, ib = 0;
            #pragma unroll
            for (int k = 0; k < KK; k++) {
                float da = pa[ia], db = pb[ib];
                bool ta = (da <= db);
                md[k] = ta ? da : db;
                mh[k] = ta ? pa[KK + ia] : pb[KK + ib];
                ia += ta ? 1 : 0;
                ib += ta ? 0 : 1;
            }

            float thr = md[KK - 1] * 1.0001f + 1e-9f;
            bool bad = false;
            if (lo > 0)  { float dz = zn - sz[lo - 1 - tl]; if (dz * dz <= thr) bad = true; }
            if (hi < nv) { float dz = sz[hi - tl] - zn;     if (dz * dz <= thr) bad = true; }

            if (bad) {
                int slot = atomicAdd(&g_nflag[b], 1);
                g_flag[base + slot]    = n;
                g_flagthr[base + slot] = thr;
            } else {
                float lm = (mh[1] + mh[2] + mh[3] + mh[4] + mh[5]) / 5.f;
                ls = smooth_l1f(hn, lm, 0.01f);
                #pragma unroll
                for (int k = 1; k < KK; k++) {
                    float nd = fmaxf(sqrtf(fmaxf(md[k], 1e-12f)), 0.001f);
                    float s  = fabsf(mh[k] - hn) / nd;
                    pensum  += fmaxf(s - 0.4f, 0.f);
                }
            }
        }

        #pragma unroll
        for (int o = 16; o > 0; o >>= 1) {
            ls     += __shfl_down_sync(0xffffffffu, ls, o);
            pensum += __shfl_down_sync(0xffffffffu, pensum, o);
        }
        if ((tid & 31) == 0) {
            atomicAdd(&sred[0], ls);
            atomicAdd(&sred[1], pensum);
        }
        __syncthreads();
        if (tid == 0) {
            atomicAdd(&g_Sls[b], sred[0]);
            atomicAdd(&g_Ssl[b], sred[1]);
        }
    } else {
        // ================= PHOTO BLOCK =================
        int warp = tid >> 5;
        int lane = tid & 31;
        if (tid < 6) sred[tid] = 0.f;
        if (tid == 6) sint = 0;
        __syncthreads();

        int total = B * N;
        int p = (blockIdx.x - windowBlocks) * 8 + warp;
        if (p < total) {
            int b = p / N;
            float klx = __ldg(kpl + 2 * p),  kly = __ldg(kpl + 2 * p + 1);
            float krx = __ldg(kpr + 2 * p),  kry = __ldg(kpr + 2 * p + 1);
            float sc  = __ldg(scores + p);

            const float* L = lg + (size_t)b * H * W;
            const float* R = rg + (size_t)b * H * W;
            float tl0, tl1, tr0, tr1;
            sample_pair(L, klx, kly, W, H, lane, tl0, tl1);
            sample_pair(R, krx, kry, W, H, lane, tr0, tr1);

            int r = lane >> 2;
            float a = 0.f;
            if (r < 7) {
                a = fabsf(tl0 - tr0);
                if ((lane & 3) < 3) a += fabsf(tl1 - tr1);
            }
            #pragma unroll
            for (int o = 16; o > 0; o >>= 1)
                a += __shfl_down_sync(0xffffffffu, a, o);

            float cl = __shfl_sync(0xffffffffu, tl1, 13);
            float cr = __shfl_sync(0xffffffffu, tr1, 13);

            if (lane == 0) {
                float diffm = a / 49.f;
                float isb   = (cl > 0.02f) ? 1.f : 0.f;
                float w     = sc * isb;
                float ydiff = fabsf(kly - kry);
                atomicAdd(&sred[0], sc);
                atomicAdd(&sred[1], ydiff * sc);
                atomicAdd(&sred[2], ydiff);
                atomicAdd(&sred[3], w);
                atomicAdd(&sred[4], diffm * w);
                atomicAdd(&sred[5], smooth_l1f(cl, cr, 1.f) * w);
                if (sc > 0.1f) atomicAdd(&sint, 1);
            }
        }
        __syncthreads();
        if (tid < 6) atomicAdd(&g_acc[tid], sred[tid]);
        if (tid == 6 && sint) atomicAdd(&g_cnt, sint);
    }
}

// ---------------- finalize (device function, run by one warp) ----------------
__device__ __forceinline__ void do_finalize(float* __restrict__ out, int B, int N, int t) {
    float s_ls = 0.f, s_sl = 0.f, s_lz = 0.f, s_ok = 0.f;
    for (int b = t; b < B; b += 32) {
        int nvi  = g_validn[b];
        float nv = (float)max(nvi, 1);
        float ok = (nvi >= 10) ? 1.f : 0.f;
        s_ls += ok * (g_Sls[b] / nv);
        s_sl += ok * (g_Ssl[b] / (nv * (float)KNN));
        s_lz += ok * fabsf(g_Sh[b] / nv);
        s_ok += ok;
    }
    float accv = (t < 6) ? g_acc[t] : 0.f;
    int   cntv = g_cnt;
    #pragma unroll
    for (int o = 16; o > 0; o >>= 1) {
        s_ls += __shfl_down_sync(0xffffffffu, s_ls, o);
        s_sl += __shfl_down_sync(0xffffffffu, s_sl, o);
        s_lz += __shfl_down_sync(0xffffffffu, s_lz, o);
        s_ok += __shfl_down_sync(0xffffffffu, s_ok, o);
    }
    float a0 = __shfl_sync(0xffffffffu, accv, 0);
    float a1 = __shfl_sync(0xffffffffu, accv, 1);
    float a2 = __shfl_sync(0xffffffffu, accv, 2);
    float a3 = __shfl_sync(0xffffffffu, accv, 3);
    float a4 = __shfl_sync(0xffffffffu, accv, 4);
    float a5 = __shfl_sync(0xffffffffu, accv, 5);
    if (t == 0) {
        float l_epi = (a0 > 0.0001f) ? (a1 / fmaxf(a0, 1e-12f))
                                     : (a2 / (float)(B * N));
        float safe = fmaxf(a3, 1e-12f);
        float l_masked    = (a3 > 0.0001f) ? (a4 / safe) : 0.f;
        float l_intensity = (a3 > 0.0001f) ? (a5 / safe) : 0.f;

        float nb = fmaxf(s_ok, 1.f);
        bool gate = (cntv >= 10) && (s_ok > 0.f);

        out[0] = l_masked + l_intensity;
        out[1] = l_epi;
        out[2] = gate ? (s_ls / nb) : 0.f;
        out[3] = gate ? (s_sl / nb) : 0.f;
        out[4] = gate ? (s_lz / nb) : 0.f;
    }
}

// ---------------- kernel 2c: flagged-point z-bounded exact scan + finalize ---
#define FLAGBX 16
__global__ void knn_flag_kernel(float* __restrict__ out, int B, int N, int totalBlocks) {
    __shared__ float sls, ssl;
    __shared__ int isLast;
    int b    = blockIdx.y;
    int tid  = threadIdx.x;        // 256 = 8 warps
    int lane = tid & 31;
    int wIdx = blockIdx.x * 8 + (tid >> 5);
    int warpsPerBatch = gridDim.x * 8;
    int base = b * SORTN;
    int nf = g_nflag[b];
    int nv = g_validn[b];
    const float4* P = gs_p + base;

    if (tid == 0) { sls = 0.f; ssl = 0.f; }
    __syncthreads();

    float lsAcc = 0.f, penAcc = 0.f;
    for (int f = wIdx; f < nf; f += warpsPerBatch) {
        int n = g_flag[base + f];
        float thr0 = g_flagthr[base + f];
        float4 me = __ldg(&P[n]);
        float xn = me.x, zn = me.y, hn = me.z, sqn = me.w;

        float dzmax = sqrtf(thr0);
        float zLo = zn - dzmax, zHi = zn + dzmax;
        int lo = 0, hiB = nv;
        while (lo < hiB) { int m = (lo + hiB) >> 1; if (__ldg(&P[m]).y < zLo) lo = m + 1; else hiB = m; }
        int jlo = lo;
        lo = jlo; hiB = nv;
        while (lo < hiB) { int m = (lo + hiB) >> 1; if (__ldg(&P[m]).y <= zHi) lo = m + 1; else hiB = m; }
        int jhi = lo;

        float d2k[KK], hk[KK];
        #pragma unroll
        for (int k = 0; k < KK; k++) { d2k[k] = 3.4e38f; hk[k] = 0.f; }

        int j = jlo + lane;
        for (; j + 96 < jhi; j += 128) {
            float4 v0 = __ldg(&P[j]);
            float4 v1 = __ldg(&P[j + 32]);
            float4 v2 = __ldg(&P[j + 64]);
            float4 v3 = __ldg(&P[j + 96]);
            float d0 = sqn + v0.w - 2.f * (xn * v0.x + zn * v0.y);
            float d1 = sqn + v1.w - 2.f * (xn * v1.x + zn * v1.y);
            float d2_ = sqn + v2.w - 2.f * (xn * v2.x + zn * v2.y);
            float d3 = sqn + v3.w - 2.f * (xn * v3.x + zn * v3.y);
            INSERT6(d0, v0.z);
            INSERT6(d1, v1.z);
            INSERT6(d2_, v2.z);
            INSERT6(d3, v3.z);
        }
        for (; j < jhi; j += 32) {
            float4 v = __ldg(&P[j]);
            float d2 = sqn + v.w - 2.f * (xn * v.x + zn * v.y);
            INSERT6(d2, v.z);
        }

        float md[KK], mh[KK];
        #pragma unroll
        for (int r = 0; r < KK; r++) {
            float v  = d2k[0];
            float mv = v;
            #pragma unroll
            for (int o = 16; o > 0; o >>= 1)
                mv = fminf(mv, __shfl_xor_sync(0xffffffffu, mv, o));
            unsigned msk = __ballot_sync(0xffffffffu, v == mv);
            int src = __ffs(msk) - 1;
            float hh0 = hk[0];
            float mhh = __shfl_sync(0xffffffffu, hh0, src);
            if (lane == src) {
                #pragma unroll
                for (int k = 0; k < KK - 1; k++) { d2k[k] = d2k[k + 1]; hk[k] = hk[k + 1]; }
                d2k[KK - 1] = 3.4e38f; hk[KK - 1] = 0.f;
            }
            md[r] = mv; mh[r] = mhh;
        }

        if (lane == 0) {
            float lm = (mh[1] + mh[2] + mh[3] + mh[4] + mh[5]) / 5.f;
            lsAcc += smooth_l1f(hn, lm, 0.01f);
            #pragma unroll
            for (int k = 1; k < KK; k++) {
                float nd = fmaxf(sqrtf(fmaxf(md[k], 1e-12f)), 0.001f);
                float s  = fabsf(mh[k] - hn) / nd;
                penAcc  += fmaxf(s - 0.4f, 0.f);
            }
        }
    }
    if (lane == 0 && (lsAcc != 0.f || penAcc != 0.f)) {
        atomicAdd(&sls, lsAcc);
        atomicAdd(&ssl, penAcc);
    }
    __syncthreads();
    if (tid == 0) {
        if (sls != 0.f || ssl != 0.f) {
            atomicAdd(&g_Sls[b], sls);
            atomicAdd(&g_Ssl[b], ssl);
        }
        __threadfence();
        int v = atomicAdd(&g_done, 1);
        isLast = (v == totalBlocks - 1) ? 1 : 0;
    }
    __syncthreads();
    if (isLast && tid < 32) {
        do_finalize(out, B, N, tid);
    }
}

// ---------------- fallback path (N > SORTN only) ----------------
__global__ void geom_fb_kernel(const float* __restrict__ kpl,
                               const float* __restrict__ kpr,
                               const float* __restrict__ scores,
                               const float* __restrict__ Q, int B, int N) {
    int p = blockIdx.x * 256 + threadIdx.x;
    if (p >= B * N) return;
    int b = p / N;
    float pmx, pmz, hh, sq;
    bool valid = geom(kpl, kpr, scores, Q + (size_t)b * 16, p, pmx, pmz, hh, sq);
    g_h[p] = hh;
    g_valid[p] = valid ? 1 : 0;
    if (valid) {
        g_x[p] = pmx; g_z[p] = pmz; g_sq[p] = sq;
        atomicAdd(&g_validn[b], 1);
        atomicAdd(&g_Sh[b], hh);
    } else {
        g_x[p] = 0.f; g_z[p] = 0.f; g_sq[p] = 4e18f;
    }
}

__global__ void photo_fb_kernel(const float* __restrict__ lg,
                                const float* __restrict__ rg,
                                const float* __restrict__ kpl,
                                const float* __restrict__ kpr,
                                const float* __restrict__ scores,
                                int B, int N, int H, int W) {
    __shared__ float sacc[6];
    __shared__ int   scnt;
    int tid  = threadIdx.x;
    int warp = tid >> 5;
    int lane = tid & 31;
    if (tid < 6) sacc[tid] = 0.f;
    if (tid == 6) scnt = 0;
    __syncthreads();

    int total = B * N;
    int p = blockIdx.x * 8 + warp;
    if (p < total) {
        int b = p / N;
        float klx = __ldg(kpl + 2 * p),  kly = __ldg(kpl + 2 * p + 1);
        float krx = __ldg(kpr + 2 * p),  kry = __ldg(kpr + 2 * p + 1);
        float sc  = __ldg(scores + p);
        const float* L = lg + (size_t)b * H * W;
        const float* R = rg + (size_t)b * H * W;
        float tl0, tl1, tr0, tr1;
        sample_pair(L, klx, kly, W, H, lane, tl0, tl1);
        sample_pair(R, krx, kry, W, H, lane, tr0, tr1);
        int r = lane >> 2;
        float a = 0.f;
        if (r < 7) {
            a = fabsf(tl0 - tr0);
            if ((lane & 3) < 3) a += fabsf(tl1 - tr1);
        }
        #pragma unroll
        for (int o = 16; o > 0; o >>= 1)
            a += __shfl_down_sync(0xffffffffu, a, o);
        float cl = __shfl_sync(0xffffffffu, tl1, 13);
        float cr = __shfl_sync(0xffffffffu, tr1, 13);
        if (lane == 0) {
            float diffm = a / 49.f;
            float isb   = (cl > 0.02f) ? 1.f : 0.f;
            float w     = sc * isb;
            float ydiff = fabsf(kly - kry);
            atomicAdd(&sacc[0], sc);
            atomicAdd(&sacc[1], ydiff * sc);
            atomicAdd(&sacc[2], ydiff);
            atomicAdd(&sacc[3], w);
            atomicAdd(&sacc[4], diffm * w);
            atomicAdd(&sacc[5], smooth_l1f(cl, cr, 1.f) * w);
            if (sc > 0.1f) atomicAdd(&scnt, 1);
        }
    }
    __syncthreads();
    if (tid < 6) atomicAdd(&g_acc[tid], sacc[tid]);
    if (tid == 6 && scnt) atomicAdd(&g_cnt, scnt);
}

__global__ void knn_brute_kernel(int B, int N) {
    __shared__ float4 tile[256];
    __shared__ float  sls, ssl;
    int b = blockIdx.y;
    int n = blockIdx.x * blockDim.x + threadIdx.x;
    int rowBase = b * N;

    bool active = false;
    float xn = 0.f, zn = 0.f, sqn = 0.f, hn = 0.f;
    if (n < N) {
        int p = rowBase + n;
        active = (g_valid[p] != 0);
        xn = g_x[p]; zn = g_z[p]; sqn = g_sq[p]; hn = g_h[p];
    }
    float d2k[KK], hk[KK];
    #pragma unroll
    for (int k = 0; k < KK; k++) { d2k[k] = 3.4e38f; hk[k] = 0.f; }
    if (threadIdx.x == 0) { sls = 0.f; ssl = 0.f; }

    for (int basem = 0; basem < N; basem += 256) {
        int m = basem + threadIdx.x;
        if (m < N) {
            int q = rowBase + m;
            tile[threadIdx.x] = make_float4(g_x[q], g_z[q], g_h[q], g_sq[q]);
        }
        __syncthreads();
        int cnt = min(256, N - basem);
        if (active) {
            for (int j = 0; j < cnt; j++) {
                float4 v = tile[j];
                float d2 = sqn + v.w - 2.f * (xn * v.x + zn * v.y);
                INSERT6(d2, v.z);
            }
        }
        __syncthreads();
    }

    float ls = 0.f, pensum = 0.f;
    if (active) {
        float lm = (hk[1] + hk[2] + hk[3] + hk[4] + hk[5]) / 5.f;
        ls = smooth_l1f(hn, lm, 0.01f);
        #pragma unroll
        for (int k = 1; k < KK; k++) {
            float nd = fmaxf(sqrtf(fmaxf(d2k[k], 1e-12f)), 0.001f);
            float s  = fabsf(hk[k] - hn) / nd;
            pensum  += fmaxf(s - 0.4f, 0.f);
        }
    }
    #pragma unroll
    for (int o = 16; o > 0; o >>= 1) {
        ls     += __shfl_down_sync(0xffffffffu, ls, o);
        pensum += __shfl_down_sync(0xffffffffu, pensum, o);
    }
    if ((threadIdx.x & 31) == 0) { atomicAdd(&sls, ls); atomicAdd(&ssl, pensum); }
    __syncthreads();
    if (threadIdx.x == 0) { atomicAdd(&g_Sls[b], sls); atomicAdd(&g_Ssl[b], ssl); }
}

__global__ void final_kernel(float* __restrict__ out, int B, int N) {
    if (threadIdx.x < 32) do_finalize(out, B, N, threadIdx.x);
}

// ---------------- launch ----------------
extern "C" void kernel_launch(void* const* d_in, const int* in_sizes, int n_in,
                              void* d_out, int out_size) {
    const float* lg     = (const float*)d_in[0];
    const float* rg     = (const float*)d_in[1];
    const float* kpl    = (const float*)d_in[2];
    const float* kpr    = (const float*)d_in[3];
    const float* scores = (const float*)d_in[4];
    const float* Q      = (const float*)d_in[5];
    float* out = (float*)d_out;

    int B = in_sizes[5] / 16;
    int N = in_sizes[4] / B;
    int HW = in_sizes[0] / B;
    int W = 1280, H = HW / W;
    if (H * W != HW) { W = 1280; H = HW / W; }
    int total = B * N;
    int blocks1 = (total + 7) / 8;

    if (N <= SORTN && B <= MAXB) {
        geom_sort_kernel<<<B, 1024>>>(kpl, kpr, scores, Q, N);
        int WX = (N + 127) / 128;
        int windowBlocks = WX * B;
        window_photo_kernel<<<windowBlocks + blocks1, 256>>>(
            lg, rg, kpl, kpr, scores, B, N, H, W, WX, windowBlocks);
        dim3 g3(FLAGBX, B);
        knn_flag_kernel<<<g3, 256>>>(out, B, N, FLAGBX * B);
    } else {
        zero_kernel<<<1, 256>>>();
        geom_fb_kernel<<<(total + 255) / 256, 256>>>(kpl, kpr, scores, Q, B, N);
        photo_fb_kernel<<<blocks1, 256>>>(lg, rg, kpl, kpr, scores, B, N, H, W);
        dim3 g2((N + 255) / 256, B);
        knn_brute_kernel<<<g2, 256>>>(B, N);
        final_kernel<<<1, 32>>>(out, B, N);
    }
}